// round 12
// baseline (speedup 1.0000x reference)
#include <cuda_runtime.h>

// EMD / min-permutation matching on GB300.
//   B=32768, N=6, D=64.
//   cost[b] = (sum sq norms) - 2 * maxAssign(G),  G[n][m] = p_n . t_m
//   out[0] = sum_b cost[b]
//
// R12 = R6 (8 lanes/batch, front-batched p loads, streamed q, smem
// re-partition tail) with G streamed to smem COLUMN-BY-COLUMN as computed,
// freeing 36 accumulator registers -> ~70 live regs -> launch_bounds(128,6)
// -> 6 CTA/SM (24 warps) instead of 5.

#define BLOCK   128
#define SLOT    44    // 36 G + 1 sq + 7 pad; 44 % 32 == 12 -> conflict-free

__global__ __launch_bounds__(BLOCK, 6)
void emd_kernel(const float* __restrict__ preds,
                const float* __restrict__ targets,
                float* __restrict__ out, int B)
{
    __shared__ float sh[BLOCK * SLOT];    // 22528 B

    const int t    = threadIdx.x;
    const int g    = blockIdx.x * BLOCK + t;
    const int bRaw = g >> 3;          // batch index
    const int j    = g & 7;           // lane within 8-thread group
    const int b = (bRaw < B) ? bRaw : (B - 1);   // clamp keeps lanes converged

    const float* pp = preds   + (size_t)b * 384 + 4 * j;
    const float* tt = targets + (size_t)b * 384 + 4 * j;
    float* slot = &sh[t * SLOT];

    // ---- 1) 12 pred loads front-batched (register resident)
    float4 pa[6], pc[6];
#pragma unroll
    for (int n = 0; n < 6; ++n) {
        pa[n] = *(const float4*)(pp + n * 64);
        pc[n] = *(const float4*)(pp + n * 64 + 32);
    }

    float sq = 0.0f;
#pragma unroll
    for (int n = 0; n < 6; ++n) {
        sq += pa[n].x*pa[n].x + pa[n].y*pa[n].y + pa[n].z*pa[n].z + pa[n].w*pa[n].w;
        sq += pc[n].x*pc[n].x + pc[n].y*pc[n].y + pc[n].z*pc[n].z + pc[n].w*pc[n].w;
    }

    // ---- 2) stream target rows; write each G column to smem immediately
    //         (frees the 36-reg accumulator block -> 6 CTA/SM)
#pragma unroll
    for (int m = 0; m < 6; ++m) {
        float4 qa = *(const float4*)(tt + m * 64);
        float4 qc = *(const float4*)(tt + m * 64 + 32);
        sq += qa.x*qa.x + qa.y*qa.y + qa.z*qa.z + qa.w*qa.w;
        sq += qc.x*qc.x + qc.y*qc.y + qc.z*qc.z + qc.w*qc.w;
#pragma unroll
        for (int n = 0; n < 6; ++n) {
            float d = pa[n].x*qa.x + pa[n].y*qa.y + pa[n].z*qa.z + pa[n].w*qa.w
                    + pc[n].x*qc.x + pc[n].y*qc.y + pc[n].z*qc.z + pc[n].w*qc.w;
            slot[n * 6 + m] = d;          // STS.32, conflict-free (stride 44)
        }
    }
    slot[36] = sq;
    __syncthreads();

    // ---- 3) one thread per batch: sum 8 partials, run DP
    float cost = 0.0f;
    if (t < BLOCK / 8) {                         // 16 batches per CTA
        const int bOut = blockIdx.x * (BLOCK / 8) + t;
        float A[37];

        {   // seed from first rotated slot
            const int rot0 = t & 7;
            const float* s0 = &sh[(t * 8 + rot0) * SLOT];
#pragma unroll
            for (int e = 0; e < 9; ++e) {
                float4 v = *(const float4*)&s0[4 * e];
                A[4*e]   = v.x;  A[4*e+1] = v.y;
                A[4*e+2] = v.z;  A[4*e+3] = v.w;
            }
            A[36] = s0[36];
        }
#pragma unroll
        for (int l = 1; l < 8; ++l) {
            const int rot = (l + t) & 7;                 // de-conflict rotation
            const float* s1 = &sh[(t * 8 + rot) * SLOT];
#pragma unroll
            for (int e = 0; e < 9; ++e) {
                float4 v = *(const float4*)&s1[4 * e];
                A[4*e]   += v.x;  A[4*e+1] += v.y;
                A[4*e+2] += v.z;  A[4*e+3] += v.w;
            }
            A[36] += s1[36];
        }

        if (bOut < B) {
            float dp[64];
            dp[0] = 0.0f;
#pragma unroll
            for (int k = 1; k <= 6; ++k) {
                const int r = k - 1;
#pragma unroll
                for (int S = 1; S < 64; ++S) {
                    if (__popc((unsigned)S) == k) {
                        float best = -3.0e38f;
#pragma unroll
                        for (int m = 0; m < 6; ++m)
                            if (S & (1 << m))
                                best = fmaxf(best, dp[S ^ (1 << m)] + A[r * 6 + m]);
                        dp[S] = best;
                    }
                }
            }
            cost = A[36] - 2.0f * dp[63];
        }
    }

    // ---- 4) reduce the 16 costs (first warp) and atomicAdd once
    if (t < 32) {
#pragma unroll
        for (int o = 8; o > 0; o >>= 1)
            cost += __shfl_down_sync(0xffffffffu, cost, o);
        if (t == 0) atomicAdd(out, cost);
    }
}

extern "C" void kernel_launch(void* const* d_in, const int* in_sizes, int n_in,
                              void* d_out, int out_size)
{
    const float* preds   = (const float*)d_in[0];
    const float* targets = (const float*)d_in[1];
    const int B = in_sizes[0] / 384;   // 6 * 64 floats per batch

    cudaMemsetAsync(d_out, 0, sizeof(float));
    const long long threads = (long long)B * 8;
    const int grid = (int)((threads + BLOCK - 1) / BLOCK);
    emd_kernel<<<grid, BLOCK>>>(preds, targets, (float*)d_out, B);
}

// round 13
// speedup vs baseline: 1.1418x; 1.1418x over previous
#include <cuda_runtime.h>

// EMD / min-permutation matching on GB300.
//   B=32768, N=6, D=64.
//   cost[b] = (sum sq norms) - 2 * maxAssign(G),  G[n][m] = p_n . t_m
//   out[0] = sum_b cost[b]
//
// R13 = R6 exactly, but lane j owns contiguous dims [8j, 8j+8) and every
// row is fetched with ONE 256-bit load (ld.global.nc.v8.f32, sm_100-family)
// instead of two LDG.128: 12 LDGs/thread instead of 24, same bytes/MLP.

#define BLOCK   128
#define SLOT    44    // 36 G + 1 sq + 7 pad; 44 % 32 == 12 -> STS.128 conflict-free

__device__ __forceinline__ void ldg256(float4& a, float4& b, const float* p) {
    asm("ld.global.nc.v8.f32 {%0,%1,%2,%3,%4,%5,%6,%7}, [%8];"
        : "=f"(a.x), "=f"(a.y), "=f"(a.z), "=f"(a.w),
          "=f"(b.x), "=f"(b.y), "=f"(b.z), "=f"(b.w)
        : "l"(p));
}

__global__ __launch_bounds__(BLOCK, 5)
void emd_kernel(const float* __restrict__ preds,
                const float* __restrict__ targets,
                float* __restrict__ out, int B)
{
    __shared__ float sh[BLOCK * SLOT];    // 22528 B

    const int t    = threadIdx.x;
    const int g    = blockIdx.x * BLOCK + t;
    const int bRaw = g >> 3;          // batch index
    const int j    = g & 7;           // lane within 8-thread group
    const int b = (bRaw < B) ? bRaw : (B - 1);   // clamp keeps lanes converged

    const float* pp = preds   + (size_t)b * 384 + 8 * j;   // dims [8j, 8j+8)
    const float* tt = targets + (size_t)b * 384 + 8 * j;

    // ---- 1) 6 pred rows, one 256-bit load each, front-batched
    float4 pa[6], pc[6];
#pragma unroll
    for (int n = 0; n < 6; ++n)
        ldg256(pa[n], pc[n], pp + n * 64);

    float sq = 0.0f;
#pragma unroll
    for (int n = 0; n < 6; ++n) {
        sq += pa[n].x*pa[n].x + pa[n].y*pa[n].y + pa[n].z*pa[n].z + pa[n].w*pa[n].w;
        sq += pc[n].x*pc[n].x + pc[n].y*pc[n].y + pc[n].z*pc[n].z + pc[n].w*pc[n].w;
    }

    float G[36];

    // ---- 2) stream target rows (one 256-bit load each), accumulate Gram + sq
#pragma unroll
    for (int m = 0; m < 6; ++m) {
        float4 qa, qc;
        ldg256(qa, qc, tt + m * 64);
        sq += qa.x*qa.x + qa.y*qa.y + qa.z*qa.z + qa.w*qa.w;
        sq += qc.x*qc.x + qc.y*qc.y + qc.z*qc.z + qc.w*qc.w;
#pragma unroll
        for (int n = 0; n < 6; ++n) {
            G[n * 6 + m] = pa[n].x*qa.x + pa[n].y*qa.y + pa[n].z*qa.z + pa[n].w*qa.w
                         + pc[n].x*qc.x + pc[n].y*qc.y + pc[n].z*qc.z + pc[n].w*qc.w;
        }
    }

    // ---- 3) write partial (G, sq) to own slot; STS.128, conflict-free
    {
        float* slot = &sh[t * SLOT];
#pragma unroll
        for (int i = 0; i < 9; ++i)
            *(float4*)&slot[4 * i] = make_float4(G[4*i], G[4*i+1], G[4*i+2], G[4*i+3]);
        slot[36] = sq;
    }
    __syncthreads();

    // ---- 4) one thread per batch: sum 8 partials, run DP
    float cost = 0.0f;
    if (t < BLOCK / 8) {                         // 16 batches per CTA
        const int bOut = blockIdx.x * (BLOCK / 8) + t;
        float A[37];

        {   // seed from first rotated slot
            const int rot0 = t & 7;
            const float* s0 = &sh[(t * 8 + rot0) * SLOT];
#pragma unroll
            for (int e = 0; e < 9; ++e) {
                float4 v = *(const float4*)&s0[4 * e];
                A[4*e]   = v.x;  A[4*e+1] = v.y;
                A[4*e+2] = v.z;  A[4*e+3] = v.w;
            }
            A[36] = s0[36];
        }
#pragma unroll
        for (int l = 1; l < 8; ++l) {
            const int rot = (l + t) & 7;                 // de-conflict rotation
            const float* s1 = &sh[(t * 8 + rot) * SLOT];
#pragma unroll
            for (int e = 0; e < 9; ++e) {
                float4 v = *(const float4*)&s1[4 * e];
                A[4*e]   += v.x;  A[4*e+1] += v.y;
                A[4*e+2] += v.z;  A[4*e+3] += v.w;
            }
            A[36] += s1[36];
        }

        if (bOut < B) {
            float dp[64];
            dp[0] = 0.0f;
#pragma unroll
            for (int k = 1; k <= 6; ++k) {
                const int r = k - 1;
#pragma unroll
                for (int S = 1; S < 64; ++S) {
                    if (__popc((unsigned)S) == k) {
                        float best = -3.0e38f;
#pragma unroll
                        for (int m = 0; m < 6; ++m)
                            if (S & (1 << m))
                                best = fmaxf(best, dp[S ^ (1 << m)] + A[r * 6 + m]);
                        dp[S] = best;
                    }
                }
            }
            cost = A[36] - 2.0f * dp[63];
        }
    }

    // ---- 5) reduce the 16 costs (first warp) and atomicAdd once
    if (t < 32) {
#pragma unroll
        for (int o = 8; o > 0; o >>= 1)
            cost += __shfl_down_sync(0xffffffffu, cost, o);
        if (t == 0) atomicAdd(out, cost);
    }
}

extern "C" void kernel_launch(void* const* d_in, const int* in_sizes, int n_in,
                              void* d_out, int out_size)
{
    const float* preds   = (const float*)d_in[0];
    const float* targets = (const float*)d_in[1];
    const int B = in_sizes[0] / 384;   // 6 * 64 floats per batch

    cudaMemsetAsync(d_out, 0, sizeof(float));
    const long long threads = (long long)B * 8;
    const int grid = (int)((threads + BLOCK - 1) / BLOCK);
    emd_kernel<<<grid, BLOCK>>>(preds, targets, (float*)d_out, B);
}